// round 1
// baseline (speedup 1.0000x reference)
#include <cuda_runtime.h>

#define NC 24
#define LH 256
#define LW 256
#define PLANE (LH*LW)
#define R 8
#define EPSF 1e-4f

// Scratch (allocation-free rule: __device__ globals)
__device__ float g_hI [NC*PLANE];
__device__ float g_hP [NC*PLANE];
__device__ float g_hIP[NC*PLANE];
__device__ float g_hII[NC*PLANE];
__device__ float g_A  [NC*PLANE];
__device__ float g_B  [NC*PLANE];

// ---------------------------------------------------------------------------
// Kernel 1: horizontal truncated window sums for I, p, I*p, I*I.
// One block per (plane,row); 256 threads = 256 columns.
// ---------------------------------------------------------------------------
__global__ void k_hbox(const float* __restrict__ p, const float* __restrict__ I)
{
    const int row = blockIdx.x;
    const int pl  = blockIdx.y;
    const int x   = threadIdx.x;

    __shared__ float sI[LW], sP[LW], sIP[LW], sII[LW];

    const int base = pl*PLANE + row*LW;
    float vi = I[base + x];
    float vp = p[base + x];
    sI[x]  = vi;
    sP[x]  = vp;
    sIP[x] = vi*vp;
    sII[x] = vi*vi;
    __syncthreads();

    const int lo = max(x - R, 0);
    const int hi = min(x + R, LW - 1);
    float a = 0.f, b = 0.f, c = 0.f, d = 0.f;
    #pragma unroll 1
    for (int i = lo; i <= hi; i++) {
        a += sI[i]; b += sP[i]; c += sIP[i]; d += sII[i];
    }
    g_hI [base + x] = a;
    g_hP [base + x] = b;
    g_hIP[base + x] = c;
    g_hII[base + x] = d;
}

// ---------------------------------------------------------------------------
// Kernel 2: vertical truncated window (sliding sum per column) + divide by
// separable count + solve A,B. Grid: (8 y-chunks of 32, NC planes), 256 thr = cols.
// ---------------------------------------------------------------------------
__global__ void k_vbox_solve()
{
    const int pl = blockIdx.y;
    const int x  = threadIdx.x;
    const int y0 = blockIdx.x * 32;

    const float* __restrict__ hI  = g_hI  + pl*PLANE;
    const float* __restrict__ hP  = g_hP  + pl*PLANE;
    const float* __restrict__ hIP = g_hIP + pl*PLANE;
    const float* __restrict__ hII = g_hII + pl*PLANE;

    // init window for row y0: rows [max(y0-R,0), min(y0+R,255)]
    float sI = 0.f, sP = 0.f, sIP = 0.f, sII = 0.f;
    {
        const int lo = max(y0 - R, 0);
        const int hi = min(y0 + R, LH - 1);
        for (int y = lo; y <= hi; y++) {
            const int o = y*LW + x;
            sI += hI[o]; sP += hP[o]; sIP += hIP[o]; sII += hII[o];
        }
    }

    const int   cx   = min(x + R, LW - 1) - max(x - R, 0) + 1;
    const float fcx  = (float)cx;

    for (int y = y0; y < y0 + 32; y++) {
        const int   cy  = min(y + R, LH - 1) - max(y - R, 0) + 1;
        const float inv = 1.0f / (fcx * (float)cy);

        const float mI  = sI  * inv;
        const float mP  = sP  * inv;
        const float mIP = sIP * inv;
        const float mII = sII * inv;

        const float cov = mIP - mI*mP;
        const float var = mII - mI*mI;
        const float A   = cov / (var + EPSF);
        const float B   = mP - A*mI;

        const int o = pl*PLANE + y*LW + x;
        g_A[o] = A;
        g_B[o] = B;

        // slide window y -> y+1: add row y+R+1, remove row y-R
        const int add = y + R + 1;
        const int sub = y - R;
        if (add <= LH - 1) {
            const int oa = add*LW + x;
            sI += hI[oa]; sP += hP[oa]; sIP += hIP[oa]; sII += hII[oa];
        }
        if (sub >= 0) {
            const int os = sub*LW + x;
            sI -= hI[os]; sP -= hP[os]; sIP -= hIP[os]; sII -= hII[os];
        }
    }
}

// ---------------------------------------------------------------------------
// Kernel 3: bilinear (half-pixel, edge-clamped == jax linear resize) upsample
// x4 of A,B fused with out = A_hr*I_hr + B_hr.
// Grid: (1024 rows, NC planes), 256 threads; each thread -> 4 consecutive X.
// For thread t, the 4 outputs X=4t..4t+3 need LR columns t-1, t, t+1 only.
// Fractional weights are the fixed x4 pattern {.625,.875,.125,.375}.
// ---------------------------------------------------------------------------
__global__ void k_apply(const float* __restrict__ Ihr, float* __restrict__ out)
{
    const int Y  = blockIdx.x;
    const int pl = blockIdx.y;
    const int t  = threadIdx.x;

    const float yf  = 0.25f * (float)Y - 0.375f;
    const int   y0  = (int)floorf(yf);
    const float wy  = yf - (float)y0;
    const int   y0c = max(y0, 0);
    const int   y1c = min(y0 + 1, LH - 1);

    const float* __restrict__ A = g_A + pl*PLANE;
    const float* __restrict__ B = g_B + pl*PLANE;

    const int xm = max(t - 1, 0);
    const int xp = min(t + 1, LW - 1);
    const int r0 = y0c*LW, r1 = y1c*LW;

    const float a0m = A[r0 + xm], a00 = A[r0 + t], a0p = A[r0 + xp];
    const float a1m = A[r1 + xm], a10 = A[r1 + t], a1p = A[r1 + xp];
    const float b0m = B[r0 + xm], b00 = B[r0 + t], b0p = B[r0 + xp];
    const float b1m = B[r1 + xm], b10 = B[r1 + t], b1p = B[r1 + xp];

    // lerp along y
    const float am = a0m + wy*(a1m - a0m);
    const float a0 = a00 + wy*(a10 - a00);
    const float ap = a0p + wy*(a1p - a0p);
    const float bm = b0m + wy*(b1m - b0m);
    const float b0 = b00 + wy*(b10 - b00);
    const float bp = b0p + wy*(b1p - b0p);

    const int idx = ((pl << 10) + Y) * 1024 + (t << 2);
    const float4 iv = *reinterpret_cast<const float4*>(Ihr + idx);

    float4 ov;
    // X=4t+0: xf = t-0.375 -> cols (t-1,t) weights (0.375,0.625)
    ov.x = (0.375f*am + 0.625f*a0)*iv.x + (0.375f*bm + 0.625f*b0);
    // X=4t+1: xf = t-0.125 -> (t-1,t) weights (0.125,0.875)
    ov.y = (0.125f*am + 0.875f*a0)*iv.y + (0.125f*bm + 0.875f*b0);
    // X=4t+2: xf = t+0.125 -> (t,t+1) weights (0.875,0.125)
    ov.z = (0.875f*a0 + 0.125f*ap)*iv.z + (0.875f*b0 + 0.125f*bp);
    // X=4t+3: xf = t+0.375 -> (t,t+1) weights (0.625,0.375)
    ov.w = (0.625f*a0 + 0.375f*ap)*iv.w + (0.625f*b0 + 0.375f*bp);

    *reinterpret_cast<float4*>(out + idx) = ov;
}

// ---------------------------------------------------------------------------
extern "C" void kernel_launch(void* const* d_in, const int* in_sizes, int n_in,
                              void* d_out, int out_size)
{
    const float* p_lr = (const float*)d_in[0];
    const float* I_lr = (const float*)d_in[1];
    const float* I_hr = (const float*)d_in[2];
    float* out = (float*)d_out;

    k_hbox      <<<dim3(LH, NC), LW>>>(p_lr, I_lr);
    k_vbox_solve<<<dim3(LH/32, NC), LW>>>();
    k_apply     <<<dim3(1024, NC), 256>>>(I_hr, out);
}